// round 14
// baseline (speedup 1.0000x reference)
#include <cuda_runtime.h>
#include <cuda_fp16.h>
#include <cstdint>

#define BATCH 64
#define SRC   512
#define HID   1024
#define HID2  2048
#define NEGV  -1e10f

// ------------------------------------------------------------------
// scratch (static device globals; no cudaMalloc allowed)
// ------------------------------------------------------------------
__device__ __align__(16) __half g_encH[SRC * BATCH * HID2];  // COMPACT row order
__device__ __align__(16) __half g_UH[HID * HID2];
__device__ float g_c[BATCH * HID];
__device__ float g_part[8 * BATCH * SRC];   // per-nc partial energies
__device__ int   g_rows[BATCH * SRC];       // global packed (b<<16|s) row list
__device__ int   g_nrows;                   // total unmasked rows (atomic-allocated)

// ------------------------------------------------------------------
static __device__ __forceinline__ uint32_t smem_u32(const void* p) {
    uint32_t a;
    asm("{ .reg .u64 t; cvta.to.shared.u64 t, %1; cvt.u32.u64 %0, t; }" : "=r"(a) : "l"(p));
    return a;
}
static __device__ __forceinline__ void cp16(uint32_t dst, const void* src) {
    asm volatile("cp.async.cg.shared.global [%0], [%1], 16;" :: "r"(dst), "l"(src));
}
#define CP_COMMIT() asm volatile("cp.async.commit_group;" ::: "memory")
#define CP_WAIT(n)  asm volatile("cp.async.wait_group %0;" :: "n"(n) : "memory")

static __device__ __forceinline__ void ldm_x4(uint32_t* r, uint32_t addr) {
    asm volatile("ldmatrix.sync.aligned.m8n8.x4.shared.b16 {%0,%1,%2,%3}, [%4];"
                 : "=r"(r[0]), "=r"(r[1]), "=r"(r[2]), "=r"(r[3]) : "r"(addr));
}
static __device__ __forceinline__ void mma_f16(float* c, const uint32_t* a,
                                               uint32_t b0, uint32_t b1) {
    asm volatile(
        "mma.sync.aligned.m16n8k16.row.col.f32.f16.f16.f32 "
        "{%0,%1,%2,%3}, {%4,%5,%6,%7}, {%8,%9}, {%0,%1,%2,%3};"
        : "+f"(c[0]), "+f"(c[1]), "+f"(c[2]), "+f"(c[3])
        : "r"(a[0]), "r"(a[1]), "r"(a[2]), "r"(a[3]), "r"(b0), "r"(b1));
}

#define SWZ(o) ((uint32_t)(o) ^ ((((uint32_t)(o)) >> 3) & 0x70))

// SMEM layout for k2: stage = A(128x64 fp16, SW128) + B(128x64)
#define STAGE_BYTES 32768
#define OFF_SB      16384
#define OFF_VS      98304                // 128 floats
#define OFF_RED     98816                // 256 floats
#define OFF_ROWS    99840                // 128 ints (packed b<<16|s)
#define SMEM_TOTAL  100352

// ------------------------------------------------------------------
// K0: per-batch mask compaction -> g_rows (atomic offset)
// ------------------------------------------------------------------
__global__ void k0_compact(const void* __restrict__ mask_raw) {
    __shared__ int sh_sidx[SRC];
    __shared__ int sh_woff[8];
    __shared__ int sh_misc[3];
    const int b = blockIdx.x, t = threadIdx.x;
    const int lane = t & 31, wid = t >> 5;
    if (t == 0) { sh_misc[0] = 0; sh_misc[1] = 0; }
    __syncthreads();
    unsigned wtest = ((const unsigned*)mask_raw)[t];
    if (wtest > 1u) atomicOr(&sh_misc[0], 1);
    __syncthreads();
    const int mode = sh_misc[0];
    #pragma unroll
    for (int half = 0; half < 2; half++) {
        int s = half * 256 + t;
        int m = mode ? (int)((const unsigned char*)mask_raw)[b * SRC + s]
                     : ((const int*)mask_raw)[b * SRC + s];
        int keep = (m == 0);
        unsigned bal = __ballot_sync(0xffffffffu, keep);
        int pre = __popc(bal & ((1u << lane) - 1u));
        if (lane == 0) sh_woff[wid] = __popc(bal);
        __syncthreads();
        if (t == 0) {
            int acc = sh_misc[1];
            #pragma unroll
            for (int i = 0; i < 8; i++) { int v = sh_woff[i]; sh_woff[i] = acc; acc += v; }
            sh_misc[1] = acc;
        }
        __syncthreads();
        if (keep) sh_sidx[sh_woff[wid] + pre] = s;
        __syncthreads();
    }
    const int cnt = sh_misc[1];
    if (t == 0) sh_misc[2] = atomicAdd(&g_nrows, cnt);
    __syncthreads();
    const int off = sh_misc[2];
    for (int j = t; j < cnt; j += 256)
        g_rows[off + j] = (b << 16) | sh_sidx[j];
}

// ------------------------------------------------------------------
// convU: U_w fp32 -> fp16 (256 blocks, 8 float4/thread)
// ------------------------------------------------------------------
__global__ void convU(const float* __restrict__ U_w) {
    size_t base = (size_t)blockIdx.x * 256 + threadIdx.x;
    #pragma unroll
    for (int k = 0; k < 8; k++) {
        size_t i = base + (size_t)k * (256 * 256);
        float4 v = ((const float4*)U_w)[i];
        __half h[4] = {__float2half_rn(v.x), __float2half_rn(v.y),
                       __float2half_rn(v.z), __float2half_rn(v.w)};
        *(uint2*)(g_UH + 4 * i) = *(uint2*)h;
    }
}

// ------------------------------------------------------------------
// convE: gather-convert 16 compact rows per block into compact g_encH.
// row_base selects the compact-row range (A: 0, B: 8192).
// ------------------------------------------------------------------
__global__ void convE(const float* __restrict__ enc, int row_base) {
    const int t = threadIdx.x;
    const int r0 = row_base + blockIdx.x * 16;
    const int nrows = g_nrows;
    if (r0 >= nrows) return;
    const int valid = min(16, nrows - r0);
    for (int r = 0; r < valid; r++) {
        int packed = g_rows[r0 + r];
        int s = packed & 0xffff, b = packed >> 16;
        const float4* src = (const float4*)(enc + (size_t)(s * BATCH + b) * HID2);
        uint2* dst = (uint2*)(g_encH + (size_t)(r0 + r) * HID2);
        #pragma unroll
        for (int i = 0; i < 2; i++) {
            int idx = t + i * 256;             // 0..511 float4s
            float4 v = src[idx];
            __half h[4] = {__float2half_rn(v.x), __float2half_rn(v.y),
                           __float2half_rn(v.z), __float2half_rn(v.w)};
            dst[idx] = *(uint2*)h;
        }
    }
}

// ------------------------------------------------------------------
// K1: g_c[b,h] = hidden[b,:].W_w[h,:] + W_b[h] + U_b[h]
// ------------------------------------------------------------------
__global__ void k1_wh(const float* __restrict__ hidden,
                      const float* __restrict__ W_w,
                      const float* __restrict__ W_b,
                      const float* __restrict__ U_b) {
    __shared__ __align__(16) float hs[8 * HID];   // 32KB
    const int htile = blockIdx.x, bg = blockIdx.y;
    const int t = threadIdx.x, w = t >> 5, lane = t & 31;
    #pragma unroll
    for (int i = 0; i < 8; i++) {
        int j = t + i * 256;
        ((float4*)hs)[j] = ((const float4*)hidden)[(size_t)bg * 2048 + j];
    }
    __syncthreads();
    #pragma unroll
    for (int r = 0; r < 4; r++) {
        const int h = htile * 32 + w * 4 + r;
        const float4* wr = (const float4*)(W_w + (size_t)h * HID);
        float acc[8] = {0.f, 0.f, 0.f, 0.f, 0.f, 0.f, 0.f, 0.f};
        #pragma unroll
        for (int i = 0; i < 8; i++) {
            float4 wv = wr[lane + i * 32];
            #pragma unroll
            for (int bb = 0; bb < 8; bb++) {
                float4 hv = ((const float4*)(hs + bb * HID))[lane + i * 32];
                acc[bb] += wv.x * hv.x + wv.y * hv.y + wv.z * hv.z + wv.w * hv.w;
            }
        }
        const float bias = W_b[h] + U_b[h];
        #pragma unroll
        for (int bb = 0; bb < 8; bb++) {
            float s = acc[bb];
            #pragma unroll
            for (int off = 16; off; off >>= 1) s += __shfl_xor_sync(0xffffffffu, s, off);
            if (lane == 0) g_c[(bg * 8 + bb) * HID + h] = s + bias;
        }
    }
}

// ------------------------------------------------------------------
// K2: fp16 mma.sync fused energy over compact rows (sequential A).
// grid (8 nc, ntiles); tile = tile_base + blockIdx.y.
// ------------------------------------------------------------------
__global__ __launch_bounds__(256, 2) void k2_energy(const float* __restrict__ v_w,
                                                    int tile_base) {
    extern __shared__ __align__(128) char smem[];
    const uint32_t sb = smem_u32(smem);
    const int nc = blockIdx.x, tile = tile_base + blockIdx.y;
    const int n0 = nc * 128;
    const int nrows = g_nrows;
    if (tile * 128 >= nrows) return;
    const int t = threadIdx.x, wid = t >> 5, lane = t & 31;
    const int wm = wid & 3, wn = wid >> 2;

    float* vs = (float*)(smem + OFF_VS);
    int* rows_sm = (int*)(smem + OFF_ROWS);
    if (t < 128) {
        vs[t] = v_w[n0 + t];
        int j = tile * 128 + t;
        rows_sm[t] = g_rows[j < nrows ? j : (nrows - 1)];
    }
    __syncthreads();

    uint32_t aBase[2], bBase[4];
    #pragma unroll
    for (int mt = 0; mt < 2; mt++)
        aBase[mt] = (uint32_t)((wm * 32 + mt * 16 + (lane & 15)) * 128 + (lane >> 4) * 16);
    #pragma unroll
    for (int gq = 0; gq < 4; gq++)
        bBase[gq] = (uint32_t)((wn * 64 + gq * 16 + (lane & 7) + ((lane >> 4) << 3)) * 128
                               + ((lane >> 3) & 1) * 16);

    float c[2][8][4];
    #pragma unroll
    for (int mt = 0; mt < 2; mt++)
        #pragma unroll
        for (int nt = 0; nt < 8; nt++)
            #pragma unroll
            for (int e = 0; e < 4; e++) c[mt][nt][e] = 0.f;

    const __half* encBase = g_encH + (size_t)(tile * 128) * HID2;

    #define DO_STAGE(KT) do {                                                   \
        const int _k0 = (KT) * 64;                                              \
        const uint32_t _sbase = sb + ((uint32_t)(KT) % 3u) * STAGE_BYTES;       \
        _Pragma("unroll")                                                       \
        for (int _i = 0; _i < 4; _i++) {                                        \
            int _idx = t + _i * 256;                                            \
            int _r = _idx >> 3, _kb = _idx & 7;                                 \
            uint32_t _so = SWZ(_r * 128 + _kb * 16);                            \
            cp16(_sbase + _so, encBase + (size_t)_r * HID2 + _k0 + _kb * 8);    \
            cp16(_sbase + OFF_SB + _so,                                         \
                 g_UH + (size_t)(n0 + _r) * HID2 + _k0 + _kb * 8);              \
        }                                                                       \
    } while (0)

    DO_STAGE(0);
    CP_COMMIT();
    DO_STAGE(1);
    CP_COMMIT();

    for (int g = 0; g < 32; g++) {
        CP_WAIT(1);
        __syncthreads();
        if (g < 30) DO_STAGE(g + 2);
        CP_COMMIT();

        const uint32_t sbase = sb + ((uint32_t)g % 3u) * STAGE_BYTES;
        #pragma unroll
        for (int ks = 0; ks < 4; ks++) {
            const uint32_t ko = (uint32_t)(ks * 32);
            uint32_t ah[2][4], bb[4][4];
            #pragma unroll
            for (int mt = 0; mt < 2; mt++) ldm_x4(ah[mt], sbase + SWZ(aBase[mt] + ko));
            #pragma unroll
            for (int gq = 0; gq < 4; gq++)
                ldm_x4(bb[gq], sbase + OFF_SB + SWZ(bBase[gq] + ko));
            #pragma unroll
            for (int mt = 0; mt < 2; mt++)
                #pragma unroll
                for (int gq = 0; gq < 4; gq++) {
                    mma_f16(c[mt][2 * gq],     ah[mt], bb[gq][0], bb[gq][1]);
                    mma_f16(c[mt][2 * gq + 1], ah[mt], bb[gq][2], bb[gq][3]);
                }
        }
    }
    #undef DO_STAGE

    // ---- epilogue: per-row c gather (L2), tanh + v-dot ----
    float esum[4] = {0.f, 0.f, 0.f, 0.f};
    #pragma unroll
    for (int mt = 0; mt < 2; mt++) {
        const int rA = wm * 32 + mt * 16 + (lane >> 2);
        const int bA = rows_sm[rA] >> 16, bB = rows_sm[rA + 8] >> 16;
        const float* cA = g_c + (size_t)bA * HID + n0;
        const float* cB = g_c + (size_t)bB * HID + n0;
        #pragma unroll
        for (int nt = 0; nt < 8; nt++) {
            const int hl = wn * 64 + nt * 8 + 2 * (lane & 3);
            float2 a2 = *(const float2*)(cA + hl);
            float2 b2 = *(const float2*)(cB + hl);
            float v0 = vs[hl], v1 = vs[hl + 1];
            float x0 = a2.x + c[mt][nt][0];
            float x1 = a2.y + c[mt][nt][1];
            float x2 = b2.x + c[mt][nt][2];
            float x3 = b2.y + c[mt][nt][3];
            float t0, t1, t2, t3;
            asm("tanh.approx.f32 %0, %1;" : "=f"(t0) : "f"(x0));
            asm("tanh.approx.f32 %0, %1;" : "=f"(t1) : "f"(x1));
            asm("tanh.approx.f32 %0, %1;" : "=f"(t2) : "f"(x2));
            asm("tanh.approx.f32 %0, %1;" : "=f"(t3) : "f"(x3));
            esum[0 + mt * 2] = fmaf(v0, t0, fmaf(v1, t1, esum[0 + mt * 2]));
            esum[1 + mt * 2] = fmaf(v0, t2, fmaf(v1, t3, esum[1 + mt * 2]));
        }
    }

    // ---- deterministic row reduction + scatter through row list ----
    #pragma unroll
    for (int i = 0; i < 4; i++) {
        esum[i] += __shfl_xor_sync(0xffffffffu, esum[i], 1);
        esum[i] += __shfl_xor_sync(0xffffffffu, esum[i], 2);
    }
    float* red = (float*)(smem + OFF_RED);
    __syncthreads();
    if ((lane & 3) == 0) {
        #pragma unroll
        for (int i = 0; i < 4; i++) {
            int row = wm * 32 + (i >> 1) * 16 + (lane >> 2) + (i & 1) * 8;
            red[wn * 128 + row] = esum[i];
        }
    }
    __syncthreads();
    if (t < 128 && tile * 128 + t < nrows) {
        int packed = rows_sm[t];
        int s = packed & 0xffff, b = packed >> 16;
        g_part[(size_t)nc * (BATCH * SRC) + b * SRC + s] = red[t] + red[128 + t];
    }
}

// ------------------------------------------------------------------
// K3: masked softmax over S per batch (sums the 8 nc partials)
// ------------------------------------------------------------------
__global__ void k3_softmax(const void* __restrict__ mask_raw, float* __restrict__ out) {
    const int b = blockIdx.x, t = threadIdx.x;
    const int lane = t & 31, wid = t >> 5;
    __shared__ int s_mode;
    __shared__ float sm[16];
    __shared__ float s_bcast;
    if (t == 0) s_mode = 0;
    __syncthreads();
    if (t < 256) {
        unsigned w = ((const unsigned*)mask_raw)[t];
        if (w > 1u) atomicOr(&s_mode, 1);
    }
    __syncthreads();
    int masked = s_mode ? (int)((const unsigned char*)mask_raw)[b * SRC + t]
                        : ((const int*)mask_raw)[b * SRC + t];
    float e;
    if (masked) {
        e = NEGV;
    } else {
        e = 0.f;
        #pragma unroll
        for (int nc = 0; nc < 8; nc++)
            e += g_part[(size_t)nc * (BATCH * SRC) + b * SRC + t];
    }

    float m = e;
    #pragma unroll
    for (int off = 16; off; off >>= 1) m = fmaxf(m, __shfl_xor_sync(0xffffffffu, m, off));
    if (lane == 0) sm[wid] = m;
    __syncthreads();
    if (wid == 0) {
        float v = (lane < 16) ? sm[lane] : -3.4e38f;
        #pragma unroll
        for (int off = 8; off; off >>= 1) v = fmaxf(v, __shfl_xor_sync(0xffffffffu, v, off));
        if (lane == 0) s_bcast = v;
    }
    __syncthreads();
    float p = __expf(e - s_bcast);
    float s = p;
    #pragma unroll
    for (int off = 16; off; off >>= 1) s += __shfl_xor_sync(0xffffffffu, s, off);
    __syncthreads();
    if (lane == 0) sm[wid] = s;
    __syncthreads();
    if (wid == 0) {
        float v = (lane < 16) ? sm[lane] : 0.f;
        #pragma unroll
        for (int off = 8; off; off >>= 1) v += __shfl_xor_sync(0xffffffffu, v, off);
        if (lane == 0) s_bcast = v;
    }
    __syncthreads();
    out[b * SRC + t] = p * __frcp_rn(s_bcast);
}

// ------------------------------------------------------------------
extern "C" void kernel_launch(void* const* d_in, const int* in_sizes, int n_in,
                              void* d_out, int out_size) {
    const float* hidden = (const float*)d_in[0];
    const float* enc    = (const float*)d_in[1];
    const void*  mask   = d_in[2];
    const float* W_w    = (const float*)d_in[3];
    const float* W_b    = (const float*)d_in[4];
    const float* U_w    = (const float*)d_in[5];
    const float* U_b    = (const float*)d_in[6];
    const float* v_w    = (const float*)d_in[7];
    float* out = (float*)d_out;

    static int init_done = 0;
    static cudaStream_t s1, s2;
    static cudaEvent_t e_start, e_misc, e_convA, e_convB;
    static void* nrows_addr;
    if (!init_done) {
        cudaFuncSetAttribute(k2_energy, cudaFuncAttributeMaxDynamicSharedMemorySize, SMEM_TOTAL);
        cudaStreamCreateWithFlags(&s1, cudaStreamNonBlocking);
        cudaStreamCreateWithFlags(&s2, cudaStreamNonBlocking);
        cudaEventCreateWithFlags(&e_start, cudaEventDisableTiming);
        cudaEventCreateWithFlags(&e_misc, cudaEventDisableTiming);
        cudaEventCreateWithFlags(&e_convA, cudaEventDisableTiming);
        cudaEventCreateWithFlags(&e_convB, cudaEventDisableTiming);
        cudaGetSymbolAddress(&nrows_addr, g_nrows);
        init_done = 1;
    }

    cudaMemsetAsync(nrows_addr, 0, sizeof(int), 0);

    // fork: convU + k1 on s1 (independent of mask/enc path)
    cudaEventRecord(e_start, 0);
    cudaStreamWaitEvent(s1, e_start, 0);
    convU<<<256, 256, 0, s1>>>(U_w);
    k1_wh<<<dim3(32, 8), 256, 0, s1>>>(hidden, W_w, W_b, U_b);
    cudaEventRecord(e_misc, s1);

    // main: k0 -> convA (critical path)
    k0_compact<<<BATCH, 256>>>(mask);
    convE<<<512, 256>>>(enc, 0);          // compact rows [0, 8192)
    cudaEventRecord(e_convA, 0);

    // s2: convB after convA (overlaps k2a; doesn't steal BW from convA)
    cudaStreamWaitEvent(s2, e_convA, 0);
    convE<<<1536, 256, 0, s2>>>(enc, 8192);   // compact rows [8192, 32768)
    cudaEventRecord(e_convB, s2);

    // k2a: tiles 0..63 (rows < 8192); needs convA (order) + k1/U (event)
    cudaStreamWaitEvent(0, e_misc, 0);
    k2_energy<<<dim3(8, 64), 256, SMEM_TOTAL>>>(v_w, 0);

    // k2b: remaining tiles; needs convB
    cudaStreamWaitEvent(0, e_convB, 0);
    k2_energy<<<dim3(8, 192), 256, SMEM_TOTAL>>>(v_w, 64);

    k3_softmax<<<BATCH, 512>>>(mask, out);
}

// round 15
// speedup vs baseline: 1.2006x; 1.2006x over previous
#include <cuda_runtime.h>
#include <cuda_fp16.h>
#include <cstdint>

#define BATCH 64
#define SRC   512
#define HID   1024
#define HID2  2048
#define NEGV  -1e10f
#define ARS   (BATCH * HID2)

// ------------------------------------------------------------------
// scratch (static device globals; no cudaMalloc allowed)
// ------------------------------------------------------------------
__device__ __align__(16) __half g_encH[SRC * BATCH * HID2];
__device__ __align__(16) __half g_UH[HID * HID2];
__device__ float g_c[BATCH * HID];
__device__ float g_part[8 * BATCH * SRC];   // per-nc partial energies
__device__ int   g_rows[BATCH * SRC];       // global packed (b<<16|s) row list
__device__ int   g_nrows;                   // total unmasked rows (atomic-allocated)

// ------------------------------------------------------------------
static __device__ __forceinline__ uint32_t smem_u32(const void* p) {
    uint32_t a;
    asm("{ .reg .u64 t; cvta.to.shared.u64 t, %1; cvt.u32.u64 %0, t; }" : "=r"(a) : "l"(p));
    return a;
}
static __device__ __forceinline__ void cp16(uint32_t dst, const void* src) {
    asm volatile("cp.async.cg.shared.global [%0], [%1], 16;" :: "r"(dst), "l"(src));
}
#define CP_COMMIT() asm volatile("cp.async.commit_group;" ::: "memory")
#define CP_WAIT(n)  asm volatile("cp.async.wait_group %0;" :: "n"(n) : "memory")

static __device__ __forceinline__ void ldm_x4(uint32_t* r, uint32_t addr) {
    asm volatile("ldmatrix.sync.aligned.m8n8.x4.shared.b16 {%0,%1,%2,%3}, [%4];"
                 : "=r"(r[0]), "=r"(r[1]), "=r"(r[2]), "=r"(r[3]) : "r"(addr));
}
static __device__ __forceinline__ void mma_f16(float* c, const uint32_t* a,
                                               uint32_t b0, uint32_t b1) {
    asm volatile(
        "mma.sync.aligned.m16n8k16.row.col.f32.f16.f16.f32 "
        "{%0,%1,%2,%3}, {%4,%5,%6,%7}, {%8,%9}, {%0,%1,%2,%3};"
        : "+f"(c[0]), "+f"(c[1]), "+f"(c[2]), "+f"(c[3])
        : "r"(a[0]), "r"(a[1]), "r"(a[2]), "r"(a[3]), "r"(b0), "r"(b1));
}

#define SWZ(o) ((uint32_t)(o) ^ ((((uint32_t)(o)) >> 3) & 0x70))

// SMEM layout for k2: stage = A(128x64 fp16, 128B rows, SW128) + B(128x64)
#define STAGE_BYTES 32768
#define OFF_SB      16384
#define OFF_VS      98304                // 128 floats
#define OFF_RED     98816                // 256 floats
#define OFF_ROWS    99840                // 128 ints (packed b<<16|s)
#define SMEM_TOTAL  100352

// ------------------------------------------------------------------
// conv: block ranges
//   [0, 64):          k0 mask compaction -> g_rows via atomic offset
//   [64, 64+4096):    enc fp32 -> fp16, 8 rows/block, SKIP masked rows
//   [64+4096, +256):  U_w fp32 -> fp16, 8 float4/thread
// ------------------------------------------------------------------
#define CONV_K0_BLOCKS  64
#define CONV_ENC_BLOCKS 4096
#define CONV_U_BLOCKS   256
#define CONV_GRID       (CONV_K0_BLOCKS + CONV_ENC_BLOCKS + CONV_U_BLOCKS)

__global__ void conv(const float* __restrict__ enc, const float* __restrict__ U_w,
                     const void* __restrict__ mask_raw) {
    __shared__ int sh_sidx[SRC];
    __shared__ int sh_woff[8];
    __shared__ int sh_misc[3];           // [0]=mode, [1]=running total, [2]=global off
    const int bx = blockIdx.x, t = threadIdx.x;

    if (bx < CONV_K0_BLOCKS) {
        const int b = bx;
        const int lane = t & 31, wid = t >> 5;
        if (t == 0) { sh_misc[0] = 0; sh_misc[1] = 0; }
        __syncthreads();
        unsigned wtest = ((const unsigned*)mask_raw)[t];
        if (wtest > 1u) atomicOr(&sh_misc[0], 1);
        __syncthreads();
        const int mode = sh_misc[0];
        #pragma unroll
        for (int half = 0; half < 2; half++) {
            int s = half * 256 + t;
            int m = mode ? (int)((const unsigned char*)mask_raw)[b * SRC + s]
                         : ((const int*)mask_raw)[b * SRC + s];
            int keep = (m == 0);
            unsigned bal = __ballot_sync(0xffffffffu, keep);
            int pre = __popc(bal & ((1u << lane) - 1u));
            if (lane == 0) sh_woff[wid] = __popc(bal);
            __syncthreads();
            if (t == 0) {
                int acc = sh_misc[1];
                #pragma unroll
                for (int i = 0; i < 8; i++) { int v = sh_woff[i]; sh_woff[i] = acc; acc += v; }
                sh_misc[1] = acc;
            }
            __syncthreads();
            if (keep) sh_sidx[sh_woff[wid] + pre] = s;
            __syncthreads();
        }
        const int cnt = sh_misc[1];
        if (t == 0) sh_misc[2] = atomicAdd(&g_nrows, cnt);
        __syncthreads();
        const int off = sh_misc[2];
        for (int j = t; j < cnt; j += 256)
            g_rows[off + j] = (b << 16) | sh_sidx[j];
        return;
    }
    if (bx < CONV_K0_BLOCKS + CONV_ENC_BLOCKS) {
        // mode detection (cheap broadcast reads)
        if (t == 0) sh_misc[0] = 0;
        __syncthreads();
        unsigned wtest = ((const unsigned*)mask_raw)[t];
        if (wtest > 1u) atomicOr(&sh_misc[0], 1);
        __syncthreads();
        const int mode = sh_misc[0];
        const int rowbase = (bx - CONV_K0_BLOCKS) * 8;
        #pragma unroll
        for (int r8 = 0; r8 < 8; r8++) {
            const int j = rowbase + r8;        // enc row id = s*BATCH + b
            const int s = j >> 6, b = j & 63;
            int m = mode ? (int)((const unsigned char*)mask_raw)[b * SRC + s]
                         : ((const int*)mask_raw)[b * SRC + s];
            if (m) continue;                   // masked row: never read by k2
            #pragma unroll
            for (int i = 0; i < 2; i++) {
                size_t e4 = (size_t)j * 512 + t + i * 256;   // float4 index
                float4 v = ((const float4*)enc)[e4];
                __half h[4] = {__float2half_rn(v.x), __float2half_rn(v.y),
                               __float2half_rn(v.z), __float2half_rn(v.w)};
                *(uint2*)(g_encH + 4 * e4) = *(uint2*)h;
            }
        }
    } else {
        size_t base = (size_t)(bx - CONV_K0_BLOCKS - CONV_ENC_BLOCKS) * 256 + t;
        #pragma unroll
        for (int k = 0; k < 8; k++) {
            size_t i = base + (size_t)k * (CONV_U_BLOCKS * 256);
            float4 v = ((const float4*)U_w)[i];
            __half h[4] = {__float2half_rn(v.x), __float2half_rn(v.y),
                           __float2half_rn(v.z), __float2half_rn(v.w)};
            *(uint2*)(g_UH + 4 * i) = *(uint2*)h;
        }
    }
}

// ------------------------------------------------------------------
// K1: g_c[b,h] = hidden[b,:].W_w[h,:] + W_b[h] + U_b[h]
// grid (32 h-tiles, 8 b-groups), 256 thr; W read once per b-group.
// Runs on a side stream concurrently with conv.
// ------------------------------------------------------------------
__global__ void k1_wh(const float* __restrict__ hidden,
                      const float* __restrict__ W_w,
                      const float* __restrict__ W_b,
                      const float* __restrict__ U_b) {
    __shared__ __align__(16) float hs[8 * HID];   // 32KB
    const int htile = blockIdx.x, bg = blockIdx.y;
    const int t = threadIdx.x, w = t >> 5, lane = t & 31;
    #pragma unroll
    for (int i = 0; i < 8; i++) {
        int j = t + i * 256;
        ((float4*)hs)[j] = ((const float4*)hidden)[(size_t)bg * 2048 + j];
    }
    __syncthreads();
    #pragma unroll
    for (int r = 0; r < 4; r++) {
        const int h = htile * 32 + w * 4 + r;
        const float4* wr = (const float4*)(W_w + (size_t)h * HID);
        float acc[8] = {0.f, 0.f, 0.f, 0.f, 0.f, 0.f, 0.f, 0.f};
        #pragma unroll
        for (int i = 0; i < 8; i++) {
            float4 wv = wr[lane + i * 32];
            #pragma unroll
            for (int bb = 0; bb < 8; bb++) {
                float4 hv = ((const float4*)(hs + bb * HID))[lane + i * 32];
                acc[bb] += wv.x * hv.x + wv.y * hv.y + wv.z * hv.z + wv.w * hv.w;
            }
        }
        const float bias = W_b[h] + U_b[h];
        #pragma unroll
        for (int bb = 0; bb < 8; bb++) {
            float s = acc[bb];
            #pragma unroll
            for (int off = 16; off; off >>= 1) s += __shfl_xor_sync(0xffffffffu, s, off);
            if (lane == 0) g_c[(bg * 8 + bb) * HID + h] = s + bias;
        }
    }
}

// ------------------------------------------------------------------
// K2: fp16 mma.sync fused energy over the GLOBAL compacted row list.
// grid (8 nc, 256 tiles): tile covers g_rows[tile*128 .. +128).
// Early-exits when tile*128 >= g_nrows. M=128 x N=128, K=2048, 32 stages.
// ------------------------------------------------------------------
static __device__ __forceinline__ void do_stage(uint32_t sb, const int* rows_sm,
                                                int kt, int t, int n0) {
    const int k0 = kt * 64;
    const uint32_t sbase = sb + ((uint32_t)kt % 3u) * STAGE_BYTES;
    #pragma unroll
    for (int i = 0; i < 4; i++) {
        int idx = t + i * 256;                 // 0..1023
        int r = idx >> 3, kb = idx & 7;
        int packed = rows_sm[r];               // LDS broadcast (8 threads share r)
        int s = packed & 0xffff, b = packed >> 16;
        uint32_t so = SWZ(r * 128 + kb * 16);
        cp16(sbase + so, g_encH + (size_t)(s * BATCH + b) * HID2 + k0 + kb * 8);
        cp16(sbase + OFF_SB + so, g_UH + (size_t)(n0 + r) * HID2 + k0 + kb * 8);
    }
}

__global__ __launch_bounds__(256, 2) void k2_energy(const float* __restrict__ v_w) {
    extern __shared__ __align__(128) char smem[];
    const uint32_t sb = smem_u32(smem);
    const int nc = blockIdx.x, tile = blockIdx.y;
    const int n0 = nc * 128;
    const int nrows = g_nrows;
    if (tile * 128 >= nrows) return;
    const int t = threadIdx.x, wid = t >> 5, lane = t & 31;
    const int wm = wid & 3, wn = wid >> 2;

    float* vs = (float*)(smem + OFF_VS);
    int* rows_sm = (int*)(smem + OFF_ROWS);
    if (t < 128) {
        vs[t] = v_w[n0 + t];
        int j = tile * 128 + t;
        rows_sm[t] = g_rows[j < nrows ? j : (nrows - 1)];
    }
    __syncthreads();

    uint32_t aBase[2], bBase[4];
    #pragma unroll
    for (int mt = 0; mt < 2; mt++)
        aBase[mt] = (uint32_t)((wm * 32 + mt * 16 + (lane & 15)) * 128 + (lane >> 4) * 16);
    #pragma unroll
    for (int gq = 0; gq < 4; gq++)
        bBase[gq] = (uint32_t)((wn * 64 + gq * 16 + (lane & 7) + ((lane >> 4) << 3)) * 128
                               + ((lane >> 3) & 1) * 16);

    float c[2][8][4];
    #pragma unroll
    for (int mt = 0; mt < 2; mt++)
        #pragma unroll
        for (int nt = 0; nt < 8; nt++)
            #pragma unroll
            for (int e = 0; e < 4; e++) c[mt][nt][e] = 0.f;

    do_stage(sb, rows_sm, 0, t, n0);
    CP_COMMIT();
    do_stage(sb, rows_sm, 1, t, n0);
    CP_COMMIT();

    for (int g = 0; g < 32; g++) {
        CP_WAIT(1);
        __syncthreads();   // stage-g data visible AND prev-iter reads done
        if (g < 30) do_stage(sb, rows_sm, g + 2, t, n0);
        CP_COMMIT();

        const uint32_t sbase = sb + ((uint32_t)g % 3u) * STAGE_BYTES;

        #pragma unroll
        for (int ks = 0; ks < 4; ks++) {
            const uint32_t ko = (uint32_t)(ks * 32);
            uint32_t ah[2][4], bb[4][4];
            #pragma unroll
            for (int mt = 0; mt < 2; mt++) ldm_x4(ah[mt], sbase + SWZ(aBase[mt] + ko));
            #pragma unroll
            for (int gq = 0; gq < 4; gq++)
                ldm_x4(bb[gq], sbase + OFF_SB + SWZ(bBase[gq] + ko));
            #pragma unroll
            for (int mt = 0; mt < 2; mt++)
                #pragma unroll
                for (int gq = 0; gq < 4; gq++) {
                    mma_f16(c[mt][2 * gq],     ah[mt], bb[gq][0], bb[gq][1]);
                    mma_f16(c[mt][2 * gq + 1], ah[mt], bb[gq][2], bb[gq][3]);
                }
        }
    }

    // ---- epilogue: per-row c gather (L2), tanh + v-dot ----
    float esum[4] = {0.f, 0.f, 0.f, 0.f};
    #pragma unroll
    for (int mt = 0; mt < 2; mt++) {
        const int rA = wm * 32 + mt * 16 + (lane >> 2);
        const int bA = rows_sm[rA] >> 16, bB = rows_sm[rA + 8] >> 16;
        const float* cA = g_c + (size_t)bA * HID + n0;
        const float* cB = g_c + (size_t)bB * HID + n0;
        #pragma unroll
        for (int nt = 0; nt < 8; nt++) {
            const int hl = wn * 64 + nt * 8 + 2 * (lane & 3);
            float2 a2 = *(const float2*)(cA + hl);
            float2 b2 = *(const float2*)(cB + hl);
            float v0 = vs[hl], v1 = vs[hl + 1];
            float x0 = a2.x + c[mt][nt][0];
            float x1 = a2.y + c[mt][nt][1];
            float x2 = b2.x + c[mt][nt][2];
            float x3 = b2.y + c[mt][nt][3];
            float t0, t1, t2, t3;
            asm("tanh.approx.f32 %0, %1;" : "=f"(t0) : "f"(x0));
            asm("tanh.approx.f32 %0, %1;" : "=f"(t1) : "f"(x1));
            asm("tanh.approx.f32 %0, %1;" : "=f"(t2) : "f"(x2));
            asm("tanh.approx.f32 %0, %1;" : "=f"(t3) : "f"(x3));
            esum[0 + mt * 2] = fmaf(v0, t0, fmaf(v1, t1, esum[0 + mt * 2]));
            esum[1 + mt * 2] = fmaf(v0, t2, fmaf(v1, t3, esum[1 + mt * 2]));
        }
    }

    // ---- deterministic row reduction + scatter through row list ----
    #pragma unroll
    for (int i = 0; i < 4; i++) {
        esum[i] += __shfl_xor_sync(0xffffffffu, esum[i], 1);
        esum[i] += __shfl_xor_sync(0xffffffffu, esum[i], 2);
    }
    float* red = (float*)(smem + OFF_RED);    // [2][128] by wn
    __syncthreads();                          // all MMA-phase smem reads done
    if ((lane & 3) == 0) {
        #pragma unroll
        for (int i = 0; i < 4; i++) {
            int row = wm * 32 + (i >> 1) * 16 + (lane >> 2) + (i & 1) * 8;
            red[wn * 128 + row] = esum[i];
        }
    }
    __syncthreads();
    if (t < 128 && tile * 128 + t < nrows) {
        int packed = rows_sm[t];
        int s = packed & 0xffff, b = packed >> 16;
        g_part[(size_t)nc * (BATCH * SRC) + b * SRC + s] = red[t] + red[128 + t];
    }
}

// ------------------------------------------------------------------
// K3: masked softmax over S per batch (sums the 8 nc partials)
// ------------------------------------------------------------------
__global__ void k3_softmax(const void* __restrict__ mask_raw, float* __restrict__ out) {
    const int b = blockIdx.x, t = threadIdx.x;
    const int lane = t & 31, wid = t >> 5;
    __shared__ int s_mode;
    __shared__ float sm[16];
    __shared__ float s_bcast;
    if (t == 0) s_mode = 0;
    __syncthreads();
    if (t < 256) {
        unsigned w = ((const unsigned*)mask_raw)[t];
        if (w > 1u) atomicOr(&s_mode, 1);
    }
    __syncthreads();
    int masked = s_mode ? (int)((const unsigned char*)mask_raw)[b * SRC + t]
                        : ((const int*)mask_raw)[b * SRC + t];
    float e;
    if (masked) {
        e = NEGV;
    } else {
        e = 0.f;
        #pragma unroll
        for (int nc = 0; nc < 8; nc++)
            e += g_part[(size_t)nc * (BATCH * SRC) + b * SRC + t];
    }

    float m = e;
    #pragma unroll
    for (int off = 16; off; off >>= 1) m = fmaxf(m, __shfl_xor_sync(0xffffffffu, m, off));
    if (lane == 0) sm[wid] = m;
    __syncthreads();
    if (wid == 0) {
        float v = (lane < 16) ? sm[lane] : -3.4e38f;
        #pragma unroll
        for (int off = 8; off; off >>= 1) v = fmaxf(v, __shfl_xor_sync(0xffffffffu, v, off));
        if (lane == 0) s_bcast = v;
    }
    __syncthreads();
    float p = __expf(e - s_bcast);
    float s = p;
    #pragma unroll
    for (int off = 16; off; off >>= 1) s += __shfl_xor_sync(0xffffffffu, s, off);
    __syncthreads();
    if (lane == 0) sm[wid] = s;
    __syncthreads();
    if (wid == 0) {
        float v = (lane < 16) ? sm[lane] : 0.f;
        #pragma unroll
        for (int off = 8; off; off >>= 1) v += __shfl_xor_sync(0xffffffffu, v, off);
        if (lane == 0) s_bcast = v;
    }
    __syncthreads();
    out[b * SRC + t] = p * __frcp_rn(s_bcast);
}

// ------------------------------------------------------------------
extern "C" void kernel_launch(void* const* d_in, const int* in_sizes, int n_in,
                              void* d_out, int out_size) {
    const float* hidden = (const float*)d_in[0];
    const float* enc    = (const float*)d_in[1];
    const void*  mask   = d_in[2];
    const float* W_w    = (const float*)d_in[3];
    const float* W_b    = (const float*)d_in[4];
    const float* U_w    = (const float*)d_in[5];
    const float* U_b    = (const float*)d_in[6];
    const float* v_w    = (const float*)d_in[7];
    float* out = (float*)d_out;

    static int init_done = 0;
    static cudaStream_t s1;
    static cudaEvent_t e0, e1;
    static void* nrows_addr;
    if (!init_done) {
        cudaFuncSetAttribute(k2_energy, cudaFuncAttributeMaxDynamicSharedMemorySize, SMEM_TOTAL);
        cudaStreamCreateWithFlags(&s1, cudaStreamNonBlocking);
        cudaEventCreateWithFlags(&e0, cudaEventDisableTiming);
        cudaEventCreateWithFlags(&e1, cudaEventDisableTiming);
        cudaGetSymbolAddress(&nrows_addr, g_nrows);
        init_done = 1;
    }

    // reset atomic row counter (captured node, runs every replay)
    cudaMemsetAsync(nrows_addr, 0, sizeof(int), 0);

    // fork: k1 on side stream, conv on main stream (independent)
    cudaEventRecord(e0, 0);
    cudaStreamWaitEvent(s1, e0, 0);
    k1_wh<<<dim3(32, 8), 256, 0, s1>>>(hidden, W_w, W_b, U_b);
    cudaEventRecord(e1, s1);

    conv<<<CONV_GRID, 256>>>(enc, U_w, mask);

    // join: k2 needs conv (encH/UH/rows) + k1 (g_c)
    cudaStreamWaitEvent(0, e1, 0);
    k2_energy<<<dim3(8, 256), 256, SMEM_TOTAL>>>(v_w);
    k3_softmax<<<BATCH, 512>>>(mask, out);
}